// round 1
// baseline (speedup 1.0000x reference)
#include <cuda_runtime.h>
#include <math.h>

#define B 8
#define C 64
#define H 256
#define W 256
#define OCH 128
#define K2 9
#define HO 128
#define WO 128
#define CK 576        // C * K2
#define TILE 32       // output positions per block in main kernel
#define OFFC 27
#define OFFP 28       // padded offset-channel count (16B-aligned rows)

// Scratch (device globals: allocation-free at runtime)
__device__ __align__(16) float g_xt[B * H * W * C];        // x in NHWC
__device__ __align__(16) float g_off[B * HO * WO * 32];    // per-pos: [0..8]=off_x, [9..17]=off_y, [18..26]=mask(sigmoid)
__device__ __align__(16) float g_w2[OCH * CK];             // weight permuted to [oc][k*64 + c]

// ---------------------------------------------------------------------------
// Kernel 0: NCHW -> NHWC transpose of x
// ---------------------------------------------------------------------------
__global__ void transpose_kernel(const float* __restrict__ x) {
    __shared__ float tile[32][33];
    int b  = blockIdx.z;
    int s0 = blockIdx.x * 32;   // spatial index (y*W + x)
    int c0 = blockIdx.y * 32;   // channel
    int tx = threadIdx.x, ty = threadIdx.y;
    const float* xb = x + b * (C * H * W);
    float* xtb = g_xt + b * (H * W * C);
#pragma unroll
    for (int i = 0; i < 32; i += 8)
        tile[ty + i][tx] = xb[(c0 + ty + i) * (H * W) + s0 + tx];
    __syncthreads();
#pragma unroll
    for (int i = 0; i < 32; i += 8)
        xtb[(s0 + ty + i) * C + c0 + tx] = tile[tx][ty + i];
}

// ---------------------------------------------------------------------------
// Kernel 0b: permute main weights (oc, c, k) -> (oc, k, c)
// ---------------------------------------------------------------------------
__global__ void permute_w_kernel(const float* __restrict__ wt) {
    int j = blockIdx.x * 256 + threadIdx.x;
    if (j >= OCH * CK) return;
    int oc = j / CK;
    int r  = j - oc * CK;
    int k  = r >> 6;
    int c  = r & 63;
    g_w2[j] = wt[oc * CK + c * K2 + k];
}

// ---------------------------------------------------------------------------
// Kernel 1: offset conv (27 out channels, 3x3 stride 2 pad 1) + sigmoid(mask)
// One thread = one output position (block = one output row of 128).
// Shared: reorganized weights ws[tap][c][ocPadded=28]  (64.5 KB dynamic)
// ---------------------------------------------------------------------------
__global__ void offset_conv_kernel(const float* __restrict__ ow,
                                   const float* __restrict__ ob) {
    extern __shared__ float ws[];  // [9][64][OFFP]
    int tid = threadIdx.x;         // 128 threads

    // zero (pad lane must be deterministic), then load reorganized
    for (int i = tid; i < K2 * C * OFFP; i += 128) ws[i] = 0.0f;
    __syncthreads();
    for (int i = tid; i < OFFC * C * K2; i += 128) {
        int oc  = i / CK;
        int rem = i - oc * CK;
        int c   = rem / K2;
        int t   = rem - c * K2;
        ws[(t * C + c) * OFFP + oc] = ow[i];
    }
    __syncthreads();

    int bh = blockIdx.x;        // b*HO + h
    int b  = bh >> 7;
    int h  = bh & 127;
    int w  = tid;

    float acc[OFFP];
#pragma unroll
    for (int o = 0; o < OFFC; o++) acc[o] = ob[o];
    acc[27] = 0.0f;

    const float* xtb = g_xt + b * (H * W * C);
    int iy0 = h * 2 - 1;
    int ix0 = w * 2 - 1;

    for (int ky = 0; ky < 3; ky++) {
        int iy = iy0 + ky;
        if (iy < 0 || iy >= H) continue;
        for (int kx = 0; kx < 3; kx++) {
            int ix = ix0 + kx;
            if (ix < 0 || ix >= W) continue;
            const float4* px4 = (const float4*)(xtb + (iy * W + ix) * C);
            const float*  wt  = ws + (ky * 3 + kx) * C * OFFP;
#pragma unroll 2
            for (int c4 = 0; c4 < 16; c4++) {
                float4 xv = px4[c4];
                float xs[4] = {xv.x, xv.y, xv.z, xv.w};
#pragma unroll
                for (int cc = 0; cc < 4; cc++) {
                    const float4* wr = (const float4*)(wt + (c4 * 4 + cc) * OFFP);
                    float xc = xs[cc];
#pragma unroll
                    for (int o4 = 0; o4 < 7; o4++) {
                        float4 wv = wr[o4];
                        acc[o4 * 4 + 0] = fmaf(xc, wv.x, acc[o4 * 4 + 0]);
                        acc[o4 * 4 + 1] = fmaf(xc, wv.y, acc[o4 * 4 + 1]);
                        acc[o4 * 4 + 2] = fmaf(xc, wv.z, acc[o4 * 4 + 2]);
                        acc[o4 * 4 + 3] = fmaf(xc, wv.w, acc[o4 * 4 + 3]);
                    }
                }
            }
        }
    }

    // sigmoid on mask channels 18..26
#pragma unroll
    for (int o = 18; o < 27; o++)
        acc[o] = 1.0f / (1.0f + __expf(-acc[o]));

    float* dst = g_off + (bh * 128 + w) * 32;
#pragma unroll
    for (int o = 0; o < 27; o++) dst[o] = acc[o];
}

// ---------------------------------------------------------------------------
// Kernel 2: deformable gather + GEMM.
// Block: 128 threads, TILE=32 output positions (one b, one h, w0..w0+31).
// Phase 1: gather sampled[p][k*64+c] into shared (288 (pos,tap) pairs;
//          warp per 72 pairs; lane handles 2 channels via float2).
// Phase 2: thread = oc; 32 accumulators over positions; LDS.128 broadcast
//          of sampled + per-thread LDG.128 of permuted weights.
// ---------------------------------------------------------------------------
__global__ void deform_main_kernel(const float* __restrict__ bias,
                                   float* __restrict__ out) {
    extern __shared__ float smem[];  // [TILE][CK]
    int tid  = threadIdx.x;
    int warp = tid >> 5;
    int lane = tid & 31;

    int blk     = blockIdx.x;       // b*512 + tileIdx
    int b       = blk >> 9;
    int tileIdx = blk & 511;
    int h       = tileIdx >> 2;
    int w0      = (tileIdx & 3) * TILE;

    const float* xtb  = g_xt + b * (H * W * C);
    const float* offb = g_off + ((b * HO + h) * WO + w0) * 32;

    float hy = (float)(h * 2 - 1);

    // -------- gather phase --------
#pragma unroll 2
    for (int i = 0; i < 72; i++) {
        int q = warp * 72 + i;      // 0..287
        int p = q / 9;
        int k = q - p * 9;

        float offx = offb[p * 32 + k];
        float offy = offb[p * 32 + 9 + k];
        float m    = offb[p * 32 + 18 + k];

        float py = offy + (float)(k / 3) + hy;
        float px = offx + (float)(k % 3) + (float)((w0 + p) * 2 - 1);

        float y0f = floorf(py), x0f = floorf(px);
        float y1f = y0f + 1.0f, x1f = x0f + 1.0f;
        float wy1 = py - y0f, wy0 = 1.0f - wy1;
        float wx1 = px - x0f, wx0 = 1.0f - wx1;

        bool vy0 = (y0f >= 0.0f) && (y0f <= (float)(H - 1));
        bool vy1 = (y1f >= 0.0f) && (y1f <= (float)(H - 1));
        bool vx0 = (x0f >= 0.0f) && (x0f <= (float)(W - 1));
        bool vx1 = (x1f >= 0.0f) && (x1f <= (float)(W - 1));

        float w00 = (vy0 && vx0) ? wy0 * wx0 : 0.0f;
        float w01 = (vy0 && vx1) ? wy0 * wx1 : 0.0f;
        float w10 = (vy1 && vx0) ? wy1 * wx0 : 0.0f;
        float w11 = (vy1 && vx1) ? wy1 * wx1 : 0.0f;

        int yi0 = min(max((int)y0f, 0), H - 1);
        int yi1 = min(max((int)y1f, 0), H - 1);
        int xi0 = min(max((int)x0f, 0), W - 1);
        int xi1 = min(max((int)x1f, 0), W - 1);

        int cch = lane * 2;
        const float2* p00 = (const float2*)(xtb + (yi0 * W + xi0) * C + cch);
        const float2* p01 = (const float2*)(xtb + (yi0 * W + xi1) * C + cch);
        const float2* p10 = (const float2*)(xtb + (yi1 * W + xi0) * C + cch);
        const float2* p11 = (const float2*)(xtb + (yi1 * W + xi1) * C + cch);
        float2 v00 = *p00, v01 = *p01, v10 = *p10, v11 = *p11;

        float r0 = w00 * v00.x + w01 * v01.x + w10 * v10.x + w11 * v11.x;
        float r1 = w00 * v00.y + w01 * v01.y + w10 * v10.y + w11 * v11.y;
        r0 *= m; r1 *= m;

        float2* d = (float2*)(smem + p * CK + k * 64 + cch);
        *d = make_float2(r0, r1);
    }
    __syncthreads();

    // -------- GEMM phase --------
    int oc = tid;  // 0..127
    float bv = bias[oc];
    float acc[TILE];
#pragma unroll
    for (int p = 0; p < TILE; p++) acc[p] = bv;

    const float4* wrow = (const float4*)(g_w2 + oc * CK);
#pragma unroll 2
    for (int ck4 = 0; ck4 < CK / 4; ck4++) {
        float4 w4 = wrow[ck4];
#pragma unroll
        for (int p = 0; p < TILE; p++) {
            float4 s4 = *(const float4*)(smem + p * CK + ck4 * 4);
            acc[p] = fmaf(w4.x, s4.x, acc[p]);
            acc[p] = fmaf(w4.y, s4.y, acc[p]);
            acc[p] = fmaf(w4.z, s4.z, acc[p]);
            acc[p] = fmaf(w4.w, s4.w, acc[p]);
        }
    }

    float* o = out + ((b * OCH + oc) * HO + h) * WO + w0;
#pragma unroll
    for (int p4 = 0; p4 < TILE / 4; p4++) {
        float4 v = make_float4(acc[p4 * 4 + 0], acc[p4 * 4 + 1],
                               acc[p4 * 4 + 2], acc[p4 * 4 + 3]);
        ((float4*)o)[p4] = v;
    }
}

// ---------------------------------------------------------------------------
extern "C" void kernel_launch(void* const* d_in, const int* in_sizes, int n_in,
                              void* d_out, int out_size) {
    const float* x    = (const float*)d_in[0];
    const float* ow   = (const float*)d_in[1];
    const float* ob   = (const float*)d_in[2];
    const float* wt   = (const float*)d_in[3];
    const float* bias = (const float*)d_in[4];
    float* out = (float*)d_out;

    // opt-in to >48KB dynamic shared (idempotent, no graph nodes)
    cudaFuncSetAttribute(offset_conv_kernel,
                         cudaFuncAttributeMaxDynamicSharedMemorySize,
                         K2 * C * OFFP * (int)sizeof(float));
    cudaFuncSetAttribute(deform_main_kernel,
                         cudaFuncAttributeMaxDynamicSharedMemorySize,
                         TILE * CK * (int)sizeof(float));

    dim3 tb(32, 8);
    dim3 tg((H * W) / 32, C / 32, B);
    transpose_kernel<<<tg, tb>>>(x);

    permute_w_kernel<<<(OCH * CK + 255) / 256, 256>>>(wt);

    offset_conv_kernel<<<B * HO, 128, K2 * C * OFFP * (int)sizeof(float)>>>(ow, ob);

    deform_main_kernel<<<B * (HO * WO / TILE), 128,
                         TILE * CK * (int)sizeof(float)>>>(bias, out);
}

// round 3
// speedup vs baseline: 2.0632x; 2.0632x over previous
#include <cuda_runtime.h>
#include <cuda_fp16.h>
#include <math.h>
#include <stdint.h>

#define B 8
#define C 64
#define H 256
#define W 256
#define OCH 128
#define K2 9
#define HO 128
#define WO 128
#define CK 576
#define OFFC 27
#define OFFP 28

// ---------------- device scratch (allocation-free) ----------------
__device__ __align__(16) float g_xt[B * H * W * C];      // x in NHWC
__device__ __align__(16) float g_off[B * HO * WO * 32];  // per-pos offsets/mask
// prepacked weights: per tap t: 16KB SW128-swizzled fp16 image [128 oc][64 c]
__device__ __align__(16) uint32_t g_wpk[9 * 4096];

__device__ __forceinline__ uint32_t smem_u32(const void* p) {
    uint32_t a;
    asm("{ .reg .u64 t; cvta.to.shared.u64 t, %1; cvt.u32.u64 %0, t; }"
        : "=r"(a) : "l"(p));
    return a;
}
__device__ __forceinline__ uint32_t sw128(uint32_t off) {
    return off ^ ((off >> 3) & 0x70);
}

// ---------------------------------------------------------------------------
// Kernel 0: NCHW -> NHWC transpose of x
// ---------------------------------------------------------------------------
__global__ void transpose_kernel(const float* __restrict__ x) {
    __shared__ float tile[32][33];
    int b  = blockIdx.z;
    int s0 = blockIdx.x * 32;
    int c0 = blockIdx.y * 32;
    int tx = threadIdx.x, ty = threadIdx.y;
    const float* xb = x + b * (C * H * W);
    float* xtb = g_xt + (size_t)b * (H * W * C);
#pragma unroll
    for (int i = 0; i < 32; i += 8)
        tile[ty + i][tx] = xb[(c0 + ty + i) * (H * W) + s0 + tx];
    __syncthreads();
#pragma unroll
    for (int i = 0; i < 32; i += 8)
        xtb[(s0 + ty + i) * C + c0 + tx] = tile[tx][ty + i];
}

// ---------------------------------------------------------------------------
// Kernel 0b: pack main weights into per-tap SW128 fp16 smem images
// ---------------------------------------------------------------------------
__global__ void wpack_kernel(const float* __restrict__ wt) {
    int j = blockIdx.x * 256 + threadIdx.x;
    if (j >= 9 * 128 * 32) return;
    int t   = j >> 12;
    int rem = j & 4095;
    int oc  = rem >> 5;
    int c2  = rem & 31;
    int c0  = c2 * 2;

    float w0 = wt[oc * CK + c0 * K2 + t];
    float w1 = wt[oc * CK + (c0 + 1) * K2 + t];
    __half2 hv = __floats2half2_rn(w0, w1);

    uint32_t off = sw128((uint32_t)(oc * 128 + c2 * 4));
    g_wpk[t * 4096 + (off >> 2)] = *(uint32_t*)&hv;
}

// ---------------------------------------------------------------------------
// Kernel 1: offset conv (27 out, 3x3 s2 p1) + sigmoid(mask)
// ---------------------------------------------------------------------------
__global__ void offset_conv_kernel(const float* __restrict__ ow,
                                   const float* __restrict__ ob) {
    extern __shared__ float ws[];  // [9][64][OFFP]
    int tid = threadIdx.x;

    for (int i = tid; i < K2 * C * OFFP; i += 128) ws[i] = 0.0f;
    __syncthreads();
    for (int i = tid; i < OFFC * C * K2; i += 128) {
        int oc  = i / CK;
        int rem = i - oc * CK;
        int c   = rem / K2;
        int t   = rem - c * K2;
        ws[(t * C + c) * OFFP + oc] = ow[i];
    }
    __syncthreads();

    int bh = blockIdx.x;
    int b  = bh >> 7;
    int h  = bh & 127;
    int w  = tid;

    float acc[OFFP];
#pragma unroll
    for (int o = 0; o < OFFC; o++) acc[o] = ob[o];
    acc[27] = 0.0f;

    const float* xtb = g_xt + (size_t)b * (H * W * C);
    int iy0 = h * 2 - 1;
    int ix0 = w * 2 - 1;

    for (int ky = 0; ky < 3; ky++) {
        int iy = iy0 + ky;
        if (iy < 0 || iy >= H) continue;
        for (int kx = 0; kx < 3; kx++) {
            int ix = ix0 + kx;
            if (ix < 0 || ix >= W) continue;
            const float4* px4 = (const float4*)(xtb + (iy * W + ix) * C);
            const float*  wt  = ws + (ky * 3 + kx) * C * OFFP;
#pragma unroll 2
            for (int c4 = 0; c4 < 16; c4++) {
                float4 xv = px4[c4];
                float xs[4] = {xv.x, xv.y, xv.z, xv.w};
#pragma unroll
                for (int cc = 0; cc < 4; cc++) {
                    const float4* wr = (const float4*)(wt + (c4 * 4 + cc) * OFFP);
                    float xc = xs[cc];
#pragma unroll
                    for (int o4 = 0; o4 < 7; o4++) {
                        float4 wv = wr[o4];
                        acc[o4 * 4 + 0] = fmaf(xc, wv.x, acc[o4 * 4 + 0]);
                        acc[o4 * 4 + 1] = fmaf(xc, wv.y, acc[o4 * 4 + 1]);
                        acc[o4 * 4 + 2] = fmaf(xc, wv.z, acc[o4 * 4 + 2]);
                        acc[o4 * 4 + 3] = fmaf(xc, wv.w, acc[o4 * 4 + 3]);
                    }
                }
            }
        }
    }

#pragma unroll
    for (int o = 18; o < 27; o++)
        acc[o] = 1.0f / (1.0f + __expf(-acc[o]));

    float* dst = g_off + ((size_t)bh * 128 + w) * 32;
#pragma unroll
    for (int o = 0; o < 27; o++) dst[o] = acc[o];
}

// ---------------------------------------------------------------------------
// Kernel 2: deformable gather + mma.sync GEMM
// Block = one (b,h): M=128 oc x N=128 pos, K=576 = 9 taps x 64 ch
// 8 warps in 2(M) x 4(N) grid; warp tile 64x32; HMMA m16n8k16 fp16->fp32
// ---------------------------------------------------------------------------
__global__ void __launch_bounds__(256, 2)
deform_mma_kernel(const float* __restrict__ bias, float* __restrict__ out) {
    __shared__ __align__(1024) char smA[16384];  // [128 oc][64 c] fp16 SW128
    __shared__ __align__(1024) char smB[16384];  // [128 pos][64 c] fp16 SW128

    int tid   = threadIdx.x;
    int warp  = tid >> 5;
    int lane  = tid & 31;
    int warpM = warp >> 2;   // 0..1
    int warpN = warp & 3;    // 0..3

    int blk = blockIdx.x;    // b*128 + h
    int b   = blk >> 7;
    int h   = blk & 127;

    uint32_t aBase = smem_u32(smA);
    uint32_t bBase = smem_u32(smB);

    // per-lane ldmatrix address components
    int q  = lane >> 3;          // matrix index 0..3
    int rr = lane & 7;           // row within 8x8 tile
    // A: row = warpM*64 + mi*16 + (q&1)*8 + rr ; kbyte = ks*32 + (q>>1)*16
    int aRow  = warpM * 64 + (q & 1) * 8 + rr;
    int aKoff = (q >> 1) * 16;
    // B: row = warpN*32 + j2*16 + (q>>1)*8 + rr ; kbyte = ks*32 + (q&1)*16
    int bRow  = warpN * 32 + (q >> 1) * 8 + rr;
    int bKoff = (q & 1) * 16;

    float acc[4][4][4];
#pragma unroll
    for (int mi = 0; mi < 4; mi++)
#pragma unroll
        for (int ni = 0; ni < 4; ni++)
#pragma unroll
            for (int e = 0; e < 4; e++) acc[mi][ni][e] = 0.0f;

    const float* xtb = g_xt + (size_t)b * (H * W * C);
    float hyf = (float)(h * 2 - 1);
    int cch = lane * 2;

    for (int t = 0; t < 9; t++) {
        // ---- stage A (prepacked weights, 16KB) ----
        {
            const float4* asrc = ((const float4*)g_wpk) + t * 1024;
            float4* adst = (float4*)smA;
#pragma unroll
            for (int j = 0; j < 4; j++)
                adst[j * 256 + tid] = asrc[j * 256 + tid];
        }

        // ---- gather tap t into B (128 pos x 64 ch fp16) ----
        float kyf = (float)(t / 3);
        float kxf = (float)(t - (t / 3) * 3);
#pragma unroll 2
        for (int i = 0; i < 16; i++) {
            int p = warp * 16 + i;
            const float* ob = g_off + ((size_t)blk * WO + p) * 32;
            float offx = ob[t];
            float offy = ob[9 + t];
            float m    = ob[18 + t];

            float py = offy + kyf + hyf;
            float px = offx + kxf + (float)(p * 2 - 1);

            float y0f = floorf(py), x0f = floorf(px);
            float y1f = y0f + 1.0f, x1f = x0f + 1.0f;
            float wy1 = py - y0f, wy0 = 1.0f - wy1;
            float wx1 = px - x0f, wx0 = 1.0f - wx1;

            bool vy0 = (y0f >= 0.0f) && (y0f <= (float)(H - 1));
            bool vy1 = (y1f >= 0.0f) && (y1f <= (float)(H - 1));
            bool vx0 = (x0f >= 0.0f) && (x0f <= (float)(W - 1));
            bool vx1 = (x1f >= 0.0f) && (x1f <= (float)(W - 1));

            float w00 = (vy0 && vx0) ? wy0 * wx0 : 0.0f;
            float w01 = (vy0 && vx1) ? wy0 * wx1 : 0.0f;
            float w10 = (vy1 && vx0) ? wy1 * wx0 : 0.0f;
            float w11 = (vy1 && vx1) ? wy1 * wx1 : 0.0f;

            int yi0 = min(max((int)y0f, 0), H - 1);
            int yi1 = min(max((int)y1f, 0), H - 1);
            int xi0 = min(max((int)x0f, 0), W - 1);
            int xi1 = min(max((int)x1f, 0), W - 1);

            float2 v00 = *(const float2*)(xtb + (yi0 * W + xi0) * C + cch);
            float2 v01 = *(const float2*)(xtb + (yi0 * W + xi1) * C + cch);
            float2 v10 = *(const float2*)(xtb + (yi1 * W + xi0) * C + cch);
            float2 v11 = *(const float2*)(xtb + (yi1 * W + xi1) * C + cch);

            float r0 = (w00 * v00.x + w01 * v01.x + w10 * v10.x + w11 * v11.x) * m;
            float r1 = (w00 * v00.y + w01 * v01.y + w10 * v10.y + w11 * v11.y) * m;

            __half2 hv = __floats2half2_rn(r0, r1);
            *(uint32_t*)(smB + sw128((uint32_t)(p * 128 + lane * 4))) = *(uint32_t*)&hv;
        }
        __syncthreads();

        // ---- MMA phase: 4 k-steps of 16 over this tap's 64 channels ----
#pragma unroll
        for (int ks = 0; ks < 4; ks++) {
            uint32_t a0[4], a1[4], a2[4], a3[4];
            uint32_t bfr[4][2];

            // load 4 A frags (one per 16-oc m-frag)
#pragma unroll
            for (int mi = 0; mi < 4; mi++) {
                uint32_t addr = aBase +
                    sw128((uint32_t)((aRow + mi * 16) * 128 + ks * 32 + aKoff));
                asm volatile(
                    "ldmatrix.sync.aligned.m8n8.x4.shared.b16 {%0,%1,%2,%3}, [%4];"
                    : "=r"(a0[mi]), "=r"(a1[mi]), "=r"(a2[mi]), "=r"(a3[mi])
                    : "r"(addr));
            }
            // load B frags: two x4 loads cover 4 n-frags
#pragma unroll
            for (int j2 = 0; j2 < 2; j2++) {
                uint32_t addr = bBase +
                    sw128((uint32_t)((bRow + j2 * 16) * 128 + ks * 32 + bKoff));
                uint32_t r0, r1, r2, r3;
                asm volatile(
                    "ldmatrix.sync.aligned.m8n8.x4.shared.b16 {%0,%1,%2,%3}, [%4];"
                    : "=r"(r0), "=r"(r1), "=r"(r2), "=r"(r3)
                    : "r"(addr));
                bfr[j2 * 2 + 0][0] = r0; bfr[j2 * 2 + 0][1] = r1;
                bfr[j2 * 2 + 1][0] = r2; bfr[j2 * 2 + 1][1] = r3;
            }

#pragma unroll
            for (int mi = 0; mi < 4; mi++) {
#pragma unroll
                for (int ni = 0; ni < 4; ni++) {
                    asm volatile(
                        "mma.sync.aligned.m16n8k16.row.col.f32.f16.f16.f32 "
                        "{%0,%1,%2,%3}, {%4,%5,%6,%7}, {%8,%9}, {%0,%1,%2,%3};"
                        : "+f"(acc[mi][ni][0]), "+f"(acc[mi][ni][1]),
                          "+f"(acc[mi][ni][2]), "+f"(acc[mi][ni][3])
                        : "r"(a0[mi]), "r"(a1[mi]), "r"(a2[mi]), "r"(a3[mi]),
                          "r"(bfr[ni][0]), "r"(bfr[ni][1]));
                }
            }
        }
        __syncthreads();
    }

    // ---- epilogue: +bias, store float2 pairs ----
#pragma unroll
    for (int mi = 0; mi < 4; mi++) {
        int oc0 = warpM * 64 + mi * 16 + (lane >> 2);
        float bv0 = bias[oc0];
        float bv1 = bias[oc0 + 8];
        float* row0 = out + (((size_t)b * OCH + oc0) * HO + h) * WO;
        float* row1 = row0 + 8 * (HO * WO);
#pragma unroll
        for (int ni = 0; ni < 4; ni++) {
            int n = warpN * 32 + ni * 8 + (lane & 3) * 2;
            *(float2*)(row0 + n) =
                make_float2(acc[mi][ni][0] + bv0, acc[mi][ni][1] + bv0);
            *(float2*)(row1 + n) =
                make_float2(acc[mi][ni][2] + bv1, acc[mi][ni][3] + bv1);
        }
    }
}

// ---------------------------------------------------------------------------
extern "C" void kernel_launch(void* const* d_in, const int* in_sizes, int n_in,
                              void* d_out, int out_size) {
    const float* x    = (const float*)d_in[0];
    const float* ow   = (const float*)d_in[1];
    const float* ob   = (const float*)d_in[2];
    const float* wt   = (const float*)d_in[3];
    const float* bias = (const float*)d_in[4];
    float* out = (float*)d_out;

    cudaFuncSetAttribute(offset_conv_kernel,
                         cudaFuncAttributeMaxDynamicSharedMemorySize,
                         K2 * C * OFFP * (int)sizeof(float));

    dim3 tb(32, 8);
    dim3 tg((H * W) / 32, C / 32, B);
    transpose_kernel<<<tg, tb>>>(x);

    wpack_kernel<<<(9 * 128 * 32 + 255) / 256, 256>>>(wt);

    offset_conv_kernel<<<B * HO, 128, K2 * C * OFFP * (int)sizeof(float)>>>(ow, ob);

    deform_mma_kernel<<<B * HO, 256>>>(bias, out);
}

// round 4
// speedup vs baseline: 2.3695x; 1.1484x over previous
#include <cuda_runtime.h>
#include <cuda_fp16.h>
#include <math.h>
#include <stdint.h>

#define B 8
#define C 64
#define H 256
#define W 256
#define OCH 128
#define K2 9
#define HO 128
#define WO 128
#define CK 576

// ---------------- device scratch (allocation-free) ----------------
__device__ __align__(16) __half g_xh[B * H * W * C];     // x in NHWC fp16
__device__ __align__(16) float g_off[B * HO * WO * 32];  // per-pos offsets/mask
__device__ __align__(16) uint32_t g_wpk[9 * 4096];       // main W: per tap [128 oc][64 c] fp16 SW128
__device__ __align__(16) uint32_t g_wo[9 * 1024];        // offset W: per tap [32 oc][64 c] fp16 SW128

__device__ __forceinline__ uint32_t smem_u32(const void* p) {
    uint32_t a;
    asm("{ .reg .u64 t; cvta.to.shared.u64 t, %1; cvt.u32.u64 %0, t; }"
        : "=r"(a) : "l"(p));
    return a;
}
__device__ __forceinline__ uint32_t sw128(uint32_t off) {
    return off ^ ((off >> 3) & 0x70);
}
#define LDMX4(r0, r1, r2, r3, addr)                                          \
    asm volatile("ldmatrix.sync.aligned.m8n8.x4.shared.b16 {%0,%1,%2,%3}, [%4];" \
                 : "=r"(r0), "=r"(r1), "=r"(r2), "=r"(r3) : "r"(addr))
#define HMMA(acc, a, b)                                                       \
    asm volatile(                                                             \
        "mma.sync.aligned.m16n8k16.row.col.f32.f16.f16.f32 "                  \
        "{%0,%1,%2,%3}, {%4,%5,%6,%7}, {%8,%9}, {%0,%1,%2,%3};"               \
        : "+f"(acc[0]), "+f"(acc[1]), "+f"(acc[2]), "+f"(acc[3])              \
        : "r"(a[0]), "r"(a[1]), "r"(a[2]), "r"(a[3]), "r"(b[0]), "r"(b[1]))

// ---------------------------------------------------------------------------
// Kernel 0: NCHW fp32 -> NHWC fp16
// ---------------------------------------------------------------------------
__global__ void transpose_kernel(const float* __restrict__ x) {
    __shared__ float tile[32][33];
    int b  = blockIdx.z;
    int s0 = blockIdx.x * 32;
    int c0 = blockIdx.y * 32;
    int tx = threadIdx.x, ty = threadIdx.y;
    const float* xb = x + b * (C * H * W);
    __half* xtb = g_xh + (size_t)b * (H * W * C);
#pragma unroll
    for (int i = 0; i < 32; i += 8)
        tile[ty + i][tx] = xb[(c0 + ty + i) * (H * W) + s0 + tx];
    __syncthreads();
#pragma unroll
    for (int i = 0; i < 32; i += 8)
        xtb[(s0 + ty + i) * C + c0 + tx] = __float2half(tile[tx][ty + i]);
}

// ---------------------------------------------------------------------------
// Kernel 0b: pack main weights -> per-tap SW128 fp16 images [128][64]
// ---------------------------------------------------------------------------
__global__ void wpack_kernel(const float* __restrict__ wt) {
    int j = blockIdx.x * 256 + threadIdx.x;
    if (j >= 9 * 128 * 32) return;
    int t   = j >> 12;
    int rem = j & 4095;
    int oc  = rem >> 5;
    int c2  = rem & 31;
    int c0  = c2 * 2;
    float w0 = wt[oc * CK + c0 * K2 + t];
    float w1 = wt[oc * CK + (c0 + 1) * K2 + t];
    __half2 hv = __floats2half2_rn(w0, w1);
    g_wpk[t * 4096 + (sw128((uint32_t)(oc * 128 + c2 * 4)) >> 2)] = *(uint32_t*)&hv;
}

// ---------------------------------------------------------------------------
// Kernel 0c: pack offset-conv weights -> per-tap SW128 fp16 images [32][64]
// (rows 27..31 zero)
// ---------------------------------------------------------------------------
__global__ void wpack_off_kernel(const float* __restrict__ ow) {
    int j = blockIdx.x * 256 + threadIdx.x;
    if (j >= 9 * 32 * 32) return;
    int t   = j >> 10;
    int rem = j & 1023;
    int oc  = rem >> 5;
    int c2  = rem & 31;
    int c0  = c2 * 2;
    float w0 = 0.0f, w1 = 0.0f;
    if (oc < 27) {
        w0 = ow[(oc * 64 + c0) * 9 + t];
        w1 = ow[(oc * 64 + c0 + 1) * 9 + t];
    }
    __half2 hv = __floats2half2_rn(w0, w1);
    g_wo[t * 1024 + (sw128((uint32_t)(oc * 128 + c2 * 4)) >> 2)] = *(uint32_t*)&hv;
}

// ---------------------------------------------------------------------------
// Kernel 1: offset conv via mma.sync. Block = (b,h): M=32(27) x N=128 x K=576.
// 8 warps, 16 positions each. Gather = strided row read (zero-padded).
// ---------------------------------------------------------------------------
__global__ void __launch_bounds__(256)
offset_mma_kernel(const float* __restrict__ ob) {
    extern __shared__ char smraw[];
    char* smb = (char*)(((uintptr_t)smraw + 1023) & ~(uintptr_t)1023);
    char* smA = smb;            // 9 * 4096 = 36864
    char* smB = smb + 36864;    // 16384

    int tid  = threadIdx.x;
    int warp = tid >> 5;
    int lane = tid & 31;

    int blk = blockIdx.x;
    int b   = blk >> 7;
    int h   = blk & 127;

    // stage all 9 A tap-images (36KB)
    {
        const float4* asrc = (const float4*)g_wo;
        float4* adst = (float4*)smA;
#pragma unroll
        for (int j = 0; j < 9; j++)
            adst[j * 256 + tid] = asrc[j * 256 + tid];
    }
    __syncthreads();

    uint32_t aB = smem_u32(smA);
    uint32_t bB = smem_u32(smB);

    int q  = lane >> 3;
    int rr = lane & 7;
    int aRowB = (q & 1) * 8 + rr;
    int aKoff = (q >> 1) * 16;
    int bRowB = warp * 16 + (q >> 1) * 8 + rr;
    int bKoff = (q & 1) * 16;

    float acc[2][2][4];
#pragma unroll
    for (int mi = 0; mi < 2; mi++)
#pragma unroll
        for (int ni = 0; ni < 2; ni++)
#pragma unroll
            for (int e = 0; e < 4; e++) acc[mi][ni][e] = 0.0f;

    const __half* xh = g_xh + (size_t)b * (H * W * C);
    int cch = lane * 2;

    for (int t = 0; t < 9; t++) {
        int ky = t / 3;
        int kx = t - ky * 3;
        int iy = 2 * h - 1 + ky;
        bool yok = (iy >= 0) && (iy < H);
        const __half* rowp = xh + (size_t)iy * (W * C) + cch;

        // gather: 16 positions per warp
#pragma unroll
        for (int i = 0; i < 16; i++) {
            int p  = warp * 16 + i;
            int ix = 2 * p - 1 + kx;
            uint32_t v = 0;
            if (yok && ix >= 0 && ix < W)
                v = *(const uint32_t*)(rowp + ix * C);
            *(uint32_t*)(smB + sw128((uint32_t)(p * 128 + lane * 4))) = v;
        }
        __syncthreads();

#pragma unroll
        for (int ks = 0; ks < 4; ks++) {
            uint32_t a[2][4];
#pragma unroll
            for (int mi = 0; mi < 2; mi++) {
                uint32_t addr = aB + t * 4096 +
                    sw128((uint32_t)((aRowB + mi * 16) * 128 + ks * 32 + aKoff));
                LDMX4(a[mi][0], a[mi][1], a[mi][2], a[mi][3], addr);
            }
            uint32_t r0, r1, r2, r3;
            {
                uint32_t addr = bB +
                    sw128((uint32_t)(bRowB * 128 + ks * 32 + bKoff));
                LDMX4(r0, r1, r2, r3, addr);
            }
            uint32_t bf[2][2] = {{r0, r1}, {r2, r3}};
#pragma unroll
            for (int mi = 0; mi < 2; mi++)
#pragma unroll
                for (int ni = 0; ni < 2; ni++)
                    HMMA(acc[mi][ni], a[mi], bf[ni]);
        }
        __syncthreads();
    }

    // epilogue: +bias, sigmoid(mask rows 18..26), store channels < 27
    int ocb  = lane >> 2;
    int posb = warp * 16 + (lane & 3) * 2;
#pragma unroll
    for (int mi = 0; mi < 2; mi++) {
#pragma unroll
        for (int eh = 0; eh < 2; eh++) {
            int oc = mi * 16 + eh * 8 + ocb;
            if (oc >= 27) continue;
            float bv = ob[oc];
            bool sig = (oc >= 18);
#pragma unroll
            for (int ni = 0; ni < 2; ni++) {
#pragma unroll
                for (int e0 = 0; e0 < 2; e0++) {
                    float v = acc[mi][ni][eh * 2 + e0] + bv;
                    if (sig) v = 1.0f / (1.0f + __expf(-v));
                    int pos = posb + ni * 8 + e0;
                    g_off[((size_t)blk * 128 + pos) * 32 + oc] = v;
                }
            }
        }
    }
}

// ---------------------------------------------------------------------------
// Kernel 2: deformable gather + mma.sync GEMM, pipelined (double-buffered A,B)
// Block = (b,h): M=128 oc x N=128 pos, K=576. 8 warps 2Mx4N, warp tile 64x32.
// ---------------------------------------------------------------------------
__global__ void __launch_bounds__(256, 2)
deform_mma_kernel(const float* __restrict__ bias, float* __restrict__ out) {
    extern __shared__ char smraw[];
    char* smb = (char*)(((uintptr_t)smraw + 1023) & ~(uintptr_t)1023);
    char* smA[2] = {smb, smb + 16384};
    char* smB[2] = {smb + 32768, smb + 49152};

    int tid   = threadIdx.x;
    int warp  = tid >> 5;
    int lane  = tid & 31;
    int warpM = warp >> 2;
    int warpN = warp & 3;

    int blk = blockIdx.x;
    int b   = blk >> 7;
    int h   = blk & 127;

    int q  = lane >> 3;
    int rr = lane & 7;
    int aRow  = warpM * 64 + (q & 1) * 8 + rr;
    int aKoff = (q >> 1) * 16;
    int bRow  = warpN * 32 + (q >> 1) * 8 + rr;
    int bKoff = (q & 1) * 16;

    float acc[4][4][4];
#pragma unroll
    for (int mi = 0; mi < 4; mi++)
#pragma unroll
        for (int ni = 0; ni < 4; ni++)
#pragma unroll
            for (int e = 0; e < 4; e++) acc[mi][ni][e] = 0.0f;

    const __half* xh = g_xh + (size_t)b * (H * W * C);
    float hyf = (float)(h * 2 - 1);
    int cch = lane * 2;

    auto stageA = [&](int t, char* dst) {
        uint32_t d = smem_u32(dst);
        const float4* src = ((const float4*)g_wpk) + t * 1024;
#pragma unroll
        for (int j = 0; j < 4; j++) {
            asm volatile("cp.async.cg.shared.global [%0], [%1], 16;"
                         :: "r"(d + (uint32_t)(j * 256 + tid) * 16),
                            "l"(src + j * 256 + tid));
        }
    };

    auto gatherTap = [&](int t, char* dstB) {
        float kyf = (float)(t / 3);
        float kxf = (float)(t - (t / 3) * 3);
#pragma unroll 2
        for (int i = 0; i < 16; i++) {
            int p = warp * 16 + i;
            const float* obp = g_off + ((size_t)blk * WO + p) * 32;
            float offx = obp[t];
            float offy = obp[9 + t];
            float m    = obp[18 + t];

            float py = offy + kyf + hyf;
            float px = offx + kxf + (float)(p * 2 - 1);

            float y0f = floorf(py), x0f = floorf(px);
            float y1f = y0f + 1.0f, x1f = x0f + 1.0f;
            float wy1 = py - y0f, wy0 = 1.0f - wy1;
            float wx1 = px - x0f, wx0 = 1.0f - wx1;

            bool vy0 = (y0f >= 0.0f) && (y0f <= (float)(H - 1));
            bool vy1 = (y1f >= 0.0f) && (y1f <= (float)(H - 1));
            bool vx0 = (x0f >= 0.0f) && (x0f <= (float)(W - 1));
            bool vx1 = (x1f >= 0.0f) && (x1f <= (float)(W - 1));

            float w00 = (vy0 && vx0) ? wy0 * wx0 : 0.0f;
            float w01 = (vy0 && vx1) ? wy0 * wx1 : 0.0f;
            float w10 = (vy1 && vx0) ? wy1 * wx0 : 0.0f;
            float w11 = (vy1 && vx1) ? wy1 * wx1 : 0.0f;

            int yi0 = min(max((int)y0f, 0), H - 1);
            int yi1 = min(max((int)y1f, 0), H - 1);
            int xi0 = min(max((int)x0f, 0), W - 1);
            int xi1 = min(max((int)x1f, 0), W - 1);

            float2 v00 = __half22float2(*(const __half2*)(xh + (yi0 * W + xi0) * C + cch));
            float2 v01 = __half22float2(*(const __half2*)(xh + (yi0 * W + xi1) * C + cch));
            float2 v10 = __half22float2(*(const __half2*)(xh + (yi1 * W + xi0) * C + cch));
            float2 v11 = __half22float2(*(const __half2*)(xh + (yi1 * W + xi1) * C + cch));

            float r0 = (w00 * v00.x + w01 * v01.x + w10 * v10.x + w11 * v11.x) * m;
            float r1 = (w00 * v00.y + w01 * v01.y + w10 * v10.y + w11 * v11.y) * m;

            __half2 hv = __floats2half2_rn(r0, r1);
            *(uint32_t*)(dstB + sw128((uint32_t)(p * 128 + lane * 4))) = *(uint32_t*)&hv;
        }
    };

    // prologue: stage tap 0
    stageA(0, smA[0]);
    gatherTap(0, smB[0]);
    asm volatile("cp.async.wait_all;" ::: "memory");
    __syncthreads();

    for (int t = 0; t < 9; t++) {
        int cur = t & 1;
        uint32_t aB = smem_u32(smA[cur]);
        uint32_t bB = smem_u32(smB[cur]);

        // ---- MMA on current tap ----
#pragma unroll
        for (int ks = 0; ks < 4; ks++) {
            uint32_t a[4][4];
#pragma unroll
            for (int mi = 0; mi < 4; mi++) {
                uint32_t addr = aB +
                    sw128((uint32_t)((aRow + mi * 16) * 128 + ks * 32 + aKoff));
                LDMX4(a[mi][0], a[mi][1], a[mi][2], a[mi][3], addr);
            }
            uint32_t bf[4][2];
#pragma unroll
            for (int j2 = 0; j2 < 2; j2++) {
                uint32_t addr = bB +
                    sw128((uint32_t)((bRow + j2 * 16) * 128 + ks * 32 + bKoff));
                uint32_t r0, r1, r2, r3;
                LDMX4(r0, r1, r2, r3, addr);
                bf[j2 * 2 + 0][0] = r0; bf[j2 * 2 + 0][1] = r1;
                bf[j2 * 2 + 1][0] = r2; bf[j2 * 2 + 1][1] = r3;
            }
#pragma unroll
            for (int mi = 0; mi < 4; mi++)
#pragma unroll
                for (int ni = 0; ni < 4; ni++)
                    HMMA(acc[mi][ni], a[mi], bf[ni]);
        }

        // ---- prefetch next tap into other buffers ----
        if (t < 8) {
            int nxt = cur ^ 1;
            stageA(t + 1, smA[nxt]);
            gatherTap(t + 1, smB[nxt]);
            asm volatile("cp.async.wait_all;" ::: "memory");
        }
        __syncthreads();
    }

    // ---- epilogue ----
#pragma unroll
    for (int mi = 0; mi < 4; mi++) {
        int oc0 = warpM * 64 + mi * 16 + (lane >> 2);
        float bv0 = bias[oc0];
        float bv1 = bias[oc0 + 8];
        float* row0 = out + (((size_t)b * OCH + oc0) * HO + h) * WO;
        float* row1 = row0 + 8 * (HO * WO);
#pragma unroll
        for (int ni = 0; ni < 4; ni++) {
            int n = warpN * 32 + ni * 8 + (lane & 3) * 2;
            *(float2*)(row0 + n) =
                make_float2(acc[mi][ni][0] + bv0, acc[mi][ni][1] + bv0);
            *(float2*)(row1 + n) =
                make_float2(acc[mi][ni][2] + bv1, acc[mi][ni][3] + bv1);
        }
    }
}

// ---------------------------------------------------------------------------
extern "C" void kernel_launch(void* const* d_in, const int* in_sizes, int n_in,
                              void* d_out, int out_size) {
    const float* x    = (const float*)d_in[0];
    const float* ow   = (const float*)d_in[1];
    const float* ob   = (const float*)d_in[2];
    const float* wt   = (const float*)d_in[3];
    const float* bias = (const float*)d_in[4];
    float* out = (float*)d_out;

    int offSmem  = 36864 + 16384 + 1024;
    int mainSmem = 65536 + 1024;
    cudaFuncSetAttribute(offset_mma_kernel,
                         cudaFuncAttributeMaxDynamicSharedMemorySize, offSmem);
    cudaFuncSetAttribute(deform_mma_kernel,
                         cudaFuncAttributeMaxDynamicSharedMemorySize, mainSmem);

    dim3 tb(32, 8);
    dim3 tg((H * W) / 32, C / 32, B);
    transpose_kernel<<<tg, tb>>>(x);

    wpack_kernel<<<(9 * 128 * 32 + 255) / 256, 256>>>(wt);
    wpack_off_kernel<<<(9 * 32 * 32 + 255) / 256, 256>>>(ow);

    offset_mma_kernel<<<B * HO, 256, offSmem>>>(ob);

    deform_mma_kernel<<<B * HO, 256, mainSmem>>>(bias, out);
}